// round 14
// baseline (speedup 1.0000x reference)
#include <cuda_runtime.h>
#include <cuda_fp16.h>
#include <cstdint>

// ConvNearestNeightbor: out[b, n*C+c, h, w] = max_k |x_pad[b,c,h-row,w-col] - nb[n,c,k]|
// R14 = R13 minus the register clamp. R13's __launch_bounds__(256,6) capped regs at 40
// -> 27-reg window spilled to local (L1 55.8%, issue 40%). Unclamped: window stays in
// registers; 8 outputs/thread amortize LDS/loop/store overhead (15 slots/output).

namespace {

constexpr int B = 16, C = 32, H = 32, W = 32, NUM = 32;
constexpr int HW = H * W;
constexpr int NSPLIT = 2;
constexpr int NPER = NUM / NSPLIT;   // 16 planes per block
constexpr int NHALF = NPER / 2;      // 8 planes per warp-group

__device__ __forceinline__ uint32_t h2bits(__half2 v) { return *reinterpret_cast<uint32_t*>(&v); }
__device__ __forceinline__ __half2 bits2h(uint32_t v) { return *reinterpret_cast<__half2*>(&v); }
__device__ __forceinline__ uint32_t habs_bits(__half2 d) { return h2bits(d) & 0x7FFF7FFFu; }
__device__ __forceinline__ uint32_t umax2(uint32_t a, uint32_t b) {
  uint32_t r;
  asm("max.u16x2 %0, %1, %2;" : "=r"(r) : "r"(a), "r"(b));
  return r;
}
__device__ __forceinline__ uint32_t hmax2b(uint32_t a, uint32_t b) {
  __half2 r = __hmax2(bits2h(a), bits2h(b));
  return h2bits(r);
}

__global__ __launch_bounds__(256) void cnn_kernel(
    const float* __restrict__ x,
    const float* __restrict__ nb,
    float* __restrict__ out) {
  __shared__ __align__(16) __half xs[34 * 36];     // fp16 halo tile
  __shared__ __align__(16) __half2 nbs[NPER][16];  // duplicated {n,n}, padded rows

  const int bc = blockIdx.x;   // 0 .. B*C-1
  const int ns = blockIdx.y;   // 0 .. NSPLIT-1
  const int c  = bc & (C - 1);
  const int b  = bc / C;
  const int tid = threadIdx.x;

  // ---- neighbors (all 16 planes of this split), duplicated into half2 ----
  if (tid < NPER * 9) {
    int nn = tid / 9;
    int k  = tid - nn * 9;
    float v = nb[(size_t)(ns * NPER + nn) * (C * 9) + c * 9 + k];
    nbs[nn][k] = __float2half2_rn(v);
  }

  // ---- x tile: 1 vector LDG per thread -> fp16, + predicated halo zeros ----
  const float* xp = x + (size_t)bc * HW;
  {
    const int lh = tid >> 3;            // 0..31
    const int lw = (tid & 7) << 2;      // 0,4,...,28
    float4 v = *(const float4*)(xp + lh * W + lw);
    __half* dst = &xs[(lh + 1) * 36 + lw + 1];
    dst[0] = __float2half_rn(v.x);
    dst[1] = __float2half_rn(v.y);
    dst[2] = __float2half_rn(v.z);
    dst[3] = __float2half_rn(v.w);
  }
  if (tid < 132) {  // halo: rows 0,33 cols 0..33; cols 0,33 rows 1..32
    int rr, cc;
    if (tid < 68)        { rr = (tid < 34) ? 0 : 33; cc = (tid < 34) ? tid : tid - 34; }
    else if (tid < 100)  { rr = tid - 68 + 1;  cc = 0; }
    else                 { rr = tid - 100 + 1; cc = 33; }
    *(unsigned short*)&xs[rr * 36 + cc] = 0;
  }
  __syncthreads();

  // ---- compute geometry: warp-group splits planes; thread = row h, 8 cols ----
  const int grp  = tid >> 7;            // 0 or 1 -> planes grp*8 .. grp*8+7
  const int wtid = tid & 127;
  const int h  = wtid >> 2;             // 0..31
  const int wq = (wtid & 3) << 3;       // 0,8,16,24

  // window: rows h..h+2 of padded tile, cols (real) wq-1 .. wq+8.
  // A[r][i] = pair at even offset (real cols wq-1+2i, wq+2i), i=0..4
  // S[r][i] = shifted pair (real cols wq+2i, wq+1+2i), i=0..3
  uint32_t A[3][5], S[3][4];
#pragma unroll
  for (int r = 0; r < 3; r++) {
    const __half* base = &xs[(h + r) * 36 + wq];  // 8B-aligned
    uint2 v01 = *(const uint2*)(base);
    uint2 v23 = *(const uint2*)(base + 4);
    uint32_t v4 = *(const uint32_t*)(base + 8);
    A[r][0] = v01.x; A[r][1] = v01.y;
    A[r][2] = v23.x; A[r][3] = v23.y;
    A[r][4] = v4;
#pragma unroll
    for (int i = 0; i < 4; i++) {
      __half2 s = __halves2half2(__high2half(bits2h(A[r][i])),
                                 __low2half(bits2h(A[r][i + 1])));
      S[r][i] = h2bits(s);
    }
  }

  float* const outp =
      out + ((size_t)(b * NUM + ns * NPER + grp * NHALF) * C + c) * HW + h * W + wq;

#pragma unroll
  for (int nn = 0; nn < NHALF; nn++) {
    const int plane = grp * NHALF + nn;
    uint32_t nv[9];
    {
      uint4 c0 = *(const uint4*)&nbs[plane][0];   // k0..k3
      uint4 c1 = *(const uint4*)&nbs[plane][4];   // k4..k7
      nv[0] = c0.x; nv[1] = c0.y; nv[2] = c0.z; nv[3] = c0.w;
      nv[4] = c1.x; nv[5] = c1.y; nv[6] = c1.z; nv[7] = c1.w;
      nv[8] = h2bits(nbs[plane][8]);
    }

    float4 o0, o1;
#pragma unroll
    for (int p = 0; p < 4; p++) {  // output pair p -> cols (wq+2p, wq+2p+1)
      uint32_t a[9];
#pragma unroll
      for (int k = 0; k < 9; k++) {
        const int r  = 2 - k / 3;
        const int cc = 2 - k % 3;              // 0 -> A[p], 1 -> S[p], 2 -> A[p+1]
        uint32_t xvv = (cc == 0) ? A[r][p] : (cc == 1) ? S[r][p] : A[r][p + 1];
        a[k] = habs_bits(__hsub2(bits2h(xvv), bits2h(nv[k])));  // HSUB2(fma)+LOP3(alu)
      }
      uint32_t hf = hmax2b(hmax2b(a[0], a[1]), hmax2b(a[2], a[3]));  // 3x fma
      uint32_t uu = umax2(umax2(a[4], a[5]), umax2(a[6], a[7]));     // 3x alu
      uu = umax2(uu, a[8]);                                          // alu
      uint32_t m = umax2(uu, hf);                                    // alu
      float2 f = __half22float2(bits2h(m));
      if (p == 0)      { o0.x = f.x; o0.y = f.y; }
      else if (p == 1) { o0.z = f.x; o0.w = f.y; }
      else if (p == 2) { o1.x = f.x; o1.y = f.y; }
      else             { o1.z = f.x; o1.w = f.y; }
    }
    float* dst = outp + (size_t)nn * C * HW;
    *(float4*)dst       = o0;
    *(float4*)(dst + 4) = o1;
  }
}

}  // namespace

extern "C" void kernel_launch(void* const* d_in, const int* in_sizes, int n_in,
                              void* d_out, int out_size) {
  const float* x  = (const float*)d_in[0];   // (B,C,H,W) fp32
  const float* nb = (const float*)d_in[1];   // (NUM,C,9) fp32
  float* out = (float*)d_out;                // (B, NUM*C, H, W) fp32
  dim3 grid(B * C, NSPLIT);
  cnn_kernel<<<grid, 256>>>(x, nb, out);
}

// round 15
// speedup vs baseline: 1.5980x; 1.5980x over previous
#include <cuda_runtime.h>
#include <cuda_fp16.h>
#include <cstdint>

// ConvNearestNeightbor: out[b, n*C+c, h, w] = max_k |x_pad[b,c,h-row,w-col] - nb[n,c,k]|
// R15: R12's pipe-balanced fp16 body, fixed launch geometry. R12's grid (512,2)@256thr
// with 6 resident blocks/SM gave waves 888+136 -> near-idle 2nd wave (~8K cyc/SMSP).
// Now: 128-thr blocks, grid (B*C, 2) split on h (16 rows each), all 32 n-planes per
// block -> 12 blocks/SM resident, 1024 blocks = ONE wave, 7v6 balance.

namespace {

constexpr int B = 16, C = 32, H = 32, W = 32, NUM = 32;
constexpr int HW = H * W;

__device__ __forceinline__ uint32_t h2bits(__half2 v) { return *reinterpret_cast<uint32_t*>(&v); }
__device__ __forceinline__ __half2 bits2h(uint32_t v) { return *reinterpret_cast<__half2*>(&v); }
__device__ __forceinline__ uint32_t habs_bits(__half2 d) { return h2bits(d) & 0x7FFF7FFFu; }
__device__ __forceinline__ uint32_t umax2(uint32_t a, uint32_t b) {
  uint32_t r;
  asm("max.u16x2 %0, %1, %2;" : "=r"(r) : "r"(a), "r"(b));
  return r;
}
__device__ __forceinline__ uint32_t hmax2b(uint32_t a, uint32_t b) {
  __half2 r = __hmax2(bits2h(a), bits2h(b));
  return h2bits(r);
}

__global__ __launch_bounds__(128) void cnn_kernel(
    const float* __restrict__ x,
    const float* __restrict__ nb,
    float* __restrict__ out) {
  __shared__ __align__(16) __half xs[18 * 36];     // 18-row halo tile (16 + 2), padded
  __shared__ __align__(16) __half2 nbs[NUM][16];   // duplicated {n,n}, all 32 planes

  const int bc = blockIdx.x;       // 0 .. B*C-1
  const int hh = blockIdx.y;       // 0/1 -> rows [hh*16, hh*16+16)
  const int c  = bc & (C - 1);
  const int b  = bc / C;
  const int tid = threadIdx.x;     // 0..127
  const int hbase = hh << 4;

  // ---- neighbors: all 32 planes, duplicated into half2 (288 entries, 3 strided passes) ----
  for (int i = tid; i < NUM * 9; i += 128) {
    int nn = i / 9;
    int k  = i - nn * 9;
    float v = nb[(size_t)nn * (C * 9) + c * 9 + k];
    nbs[nn][k] = __float2half2_rn(v);
  }

  // ---- x tile: interior = 1 LDG.128/thread; top/bottom halo rows are REAL data ----
  const float* xp = x + (size_t)bc * HW;
  const int lh = tid >> 3;            // 0..15
  const int wq = (tid & 7) << 2;      // 0,4,...,28
  {
    float4 v = *(const float4*)(xp + (hbase + lh) * W + wq);
    __half* dst = &xs[(lh + 1) * 36 + wq + 1];
    dst[0] = __float2half_rn(v.x);
    dst[1] = __float2half_rn(v.y);
    dst[2] = __float2half_rn(v.z);
    dst[3] = __float2half_rn(v.w);
  }
  if (tid < 68) {        // rows local 0 and 17 (global hbase-1, hbase+16): real or zero
    int rr = (tid < 34) ? 0 : 17;
    int cl = (tid < 34) ? tid : tid - 34;   // local col 0..33
    int grow = hbase + rr - 1;
    int gcol = cl - 1;
    float v = 0.f;
    if ((unsigned)grow < (unsigned)H && (unsigned)gcol < (unsigned)W)
      v = xp[grow * W + gcol];
    xs[rr * 36 + cl] = __float2half_rn(v);
  } else if (tid < 100) {  // side cols local 0 and 33 for rows 1..16: always zero
    int t = tid - 68;                 // 0..31
    int rr = (t & 15) + 1;            // 1..16
    int cl = (t < 16) ? 0 : 33;
    *(unsigned short*)&xs[rr * 36 + cl] = 0;
  }
  __syncthreads();

  // ---- window: 5 sliding half2 pairs per row (cols local wq .. wq+5) ----
  uint32_t pr[3][5];
#pragma unroll
  for (int r = 0; r < 3; r++) {
    const __half* base = &xs[(lh + r) * 36 + wq];   // 8B-aligned (wq even, row 72B)
    uint2 v01 = *(const uint2*)base;                // pairs {0,1},{2,3}
    uint32_t v45 = *(const uint32_t*)(base + 4);    // pair {4,5}
    pr[r][0] = v01.x;
    pr[r][2] = v01.y;
    pr[r][4] = v45;
    __half2 s1 = __halves2half2(__high2half(bits2h(v01.x)), __low2half(bits2h(v01.y)));
    __half2 s3 = __halves2half2(__high2half(bits2h(v01.y)), __low2half(bits2h(v45)));
    pr[r][1] = h2bits(s1);
    pr[r][3] = h2bits(s3);
  }

  float* const outp =
      out + ((size_t)b * NUM * C + c) * HW + (hbase + lh) * W + wq;

#pragma unroll 4
  for (int nn = 0; nn < NUM; nn++) {
    uint32_t nv[9];
    {
      uint4 c0 = *(const uint4*)&nbs[nn][0];   // k0..k3
      uint4 c1 = *(const uint4*)&nbs[nn][4];   // k4..k7
      nv[0] = c0.x; nv[1] = c0.y; nv[2] = c0.z; nv[3] = c0.w;
      nv[4] = c1.x; nv[5] = c1.y; nv[6] = c1.z; nv[7] = c1.w;
      nv[8] = h2bits(nbs[nn][8]);
    }

    uint32_t m[2];  // p=0 -> outputs (0,1); p=1 -> outputs (2,3)
#pragma unroll
    for (int p = 0; p < 2; p++) {
      uint32_t a[9];
#pragma unroll
      for (int k = 0; k < 9; k++) {
        const int r  = 2 - k / 3;
        const int cc = 2 - k % 3;
        a[k] = habs_bits(__hsub2(bits2h(pr[r][cc + 2 * p]), bits2h(nv[k])));
      }
      uint32_t hf = hmax2b(hmax2b(a[0], a[1]), hmax2b(a[2], a[3]));  // fma pipe
      uint32_t uu = umax2(umax2(a[4], a[5]), umax2(a[6], a[7]));     // alu pipe
      uu = umax2(uu, a[8]);
      m[p] = umax2(uu, hf);
    }

    float2 f01 = __half22float2(bits2h(m[0]));
    float2 f23 = __half22float2(bits2h(m[1]));
    *(float4*)(outp + (size_t)nn * C * HW) =
        make_float4(f01.x, f01.y, f23.x, f23.y);
  }
}

}  // namespace

extern "C" void kernel_launch(void* const* d_in, const int* in_sizes, int n_in,
                              void* d_out, int out_size) {
  const float* x  = (const float*)d_in[0];   // (B,C,H,W) fp32
  const float* nb = (const float*)d_in[1];   // (NUM,C,9) fp32
  float* out = (float*)d_out;                // (B, NUM*C, H, W) fp32
  dim3 grid(B * C, 2);
  cnn_kernel<<<grid, 128>>>(x, nb, out);
}